// round 9
// baseline (speedup 1.0000x reference)
#include <cuda_runtime.h>
#include <cuda_bf16.h>
#include <cstdint>

#define BATCH 256
#define EMBED 512
#define NCLS 100000
#define NSUB 3
#define NSROWS (NCLS*NSUB)

#define NT 96       // subcenter rows per CTA (= 32 classes)
#define KC 64       // K chunk
#define CHUNKS 8
#define STAGES 3
#define THREADS 512
#define NCTAS (NCLS/32)     // 3125
#define EPI_STRIDE 49

#define COSM 0.8775825618903728f
#define SINM 0.479425538604203f
#define THv (-0.8775825618903728f)
#define MMc 0.2397127693021015f
#define SCALE 64.0f

#define SROW 72     // A smem row stride (bf16 elems): 144B
#define SROWB 72    // B smem row stride (fp32 words): 288B
#define A_STAGE_BYTES (256*SROW*2)       // 36864
#define B_STAGE_BYTES (NT*SROWB*4)       // 27648
#define STAGE_BYTES   (A_STAGE_BYTES + B_STAGE_BYTES)
#define PIPE_BYTES    (STAGES*STAGE_BYTES)
#define SMEM_BYTES    (PIPE_BYTES + NT*4)

__device__ __nv_bfloat16 g_ebf[BATCH*EMBED];
__device__ float g_sumexp[BATCH];
__device__ float g_lablogit[BATCH];
__device__ float g_expadj[BATCH];
__device__ unsigned int g_ticket;

// fast exp via FMA-pipe polynomial (avoid MUFU.EX2 throughput wall)
__device__ __forceinline__ float fexp(float x){
    float y = x * 1.4426950408889634f;
    int   n = __float2int_rn(y);
    float f = y - (float)n;
    float p = fmaf(f, 1.3333558e-3f, 9.6181291e-3f);
    p = fmaf(f, p, 5.5504109e-2f);
    p = fmaf(f, p, 2.4022651e-1f);
    p = fmaf(f, p, 6.9314718e-1f);
    p = fmaf(f, p, 1.0f);
    return p * __int_as_float((n + 127) << 23);
}

__device__ __forceinline__ uint32_t smem_u32(const void* p){
    return (uint32_t)__cvta_generic_to_shared(p);
}

// kernel 1 (fused): blocks 0..255 normalize embeddings -> bf16 scratch;
// blocks 256..319: exact fp32 label logits + sumexp correction (1 warp/row)
__global__ void prep_label(const float* __restrict__ emb,
                           const float* __restrict__ W,
                           const void*  __restrict__ labels_raw){
    if (blockIdx.x < 256){
        int row = blockIdx.x;
        int t = threadIdx.x;    // 128
        float4 v = reinterpret_cast<const float4*>(emb + (size_t)row*EMBED)[t];
        float ss = v.x*v.x + v.y*v.y + v.z*v.z + v.w*v.w;
        #pragma unroll
        for (int o=16;o;o>>=1) ss += __shfl_xor_sync(0xffffffffu, ss, o);
        __shared__ float wss[4];
        if ((t & 31) == 0) wss[t>>5] = ss;
        __syncthreads();
        float tot = wss[0]+wss[1]+wss[2]+wss[3];
        float inv = 1.0f / fmaxf(sqrtf(tot), 1e-12f);
        __nv_bfloat162 p0 = __float22bfloat162_rn(make_float2(v.x*inv, v.y*inv));
        __nv_bfloat162 p1 = __float22bfloat162_rn(make_float2(v.z*inv, v.w*inv));
        uint2 u;
        u.x = *reinterpret_cast<uint32_t*>(&p0);
        u.y = *reinterpret_cast<uint32_t*>(&p1);
        reinterpret_cast<uint2*>(g_ebf + (size_t)row*EMBED)[t] = u;
        if (t == 0) g_sumexp[row] = 0.0f;
        return;
    }
    // label part: 64 blocks x 4 warps = 256 rows
    int row  = (blockIdx.x - 256)*4 + (threadIdx.x >> 5);
    int lane = threadIdx.x & 31;

    const long long* l64 = (const long long*)labels_raw;
    const int*       l32 = (const int*)labels_raw;
    bool is64 = true;
    #pragma unroll
    for (int i=0;i<8;i++){
        long long v = l64[i];
        if (v < 0 || v >= (long long)NCLS) is64 = false;
    }
    long long lab = is64 ? l64[row] : (long long)l32[row];

    const float* e  = emb + (size_t)row*EMBED;
    const float* w0 = W   + (size_t)lab*NSUB*EMBED;

    float ess = 0.0f;
    float dot0=0.f, dot1=0.f, dot2=0.f;
    float ws0=0.f, ws1=0.f, ws2=0.f;
    for (int k = lane; k < EMBED; k += 32){
        float ev = e[k];
        ess = fmaf(ev, ev, ess);
        float a = w0[k];
        float b = w0[EMBED + k];
        float c = w0[2*EMBED + k];
        dot0 = fmaf(ev, a, dot0); ws0 = fmaf(a, a, ws0);
        dot1 = fmaf(ev, b, dot1); ws1 = fmaf(b, b, ws1);
        dot2 = fmaf(ev, c, dot2); ws2 = fmaf(c, c, ws2);
    }
    #pragma unroll
    for (int o=16;o;o>>=1){
        ess  += __shfl_xor_sync(0xffffffffu, ess,  o);
        dot0 += __shfl_xor_sync(0xffffffffu, dot0, o);
        dot1 += __shfl_xor_sync(0xffffffffu, dot1, o);
        dot2 += __shfl_xor_sync(0xffffffffu, dot2, o);
        ws0  += __shfl_xor_sync(0xffffffffu, ws0,  o);
        ws1  += __shfl_xor_sync(0xffffffffu, ws1,  o);
        ws2  += __shfl_xor_sync(0xffffffffu, ws2,  o);
    }
    if (lane == 0){
        float einv = 1.0f / fmaxf(sqrtf(ess), 1e-12f);
        float c0 = dot0 * einv / fmaxf(sqrtf(ws0), 1e-12f);
        float c1 = dot1 * einv / fmaxf(sqrtf(ws1), 1e-12f);
        float c2 = dot2 * einv / fmaxf(sqrtf(ws2), 1e-12f);
        float cs = fmaxf(c0, fmaxf(c1, c2));
        float sine = sqrtf(fmaxf(1.0f - cs*cs, 0.0f));
        float phi = (cs > THv) ? (cs*COSM - sine*SINM) : (cs - MMc);
        float ll = SCALE * phi;
        g_lablogit[row] = ll;
        g_expadj[row] = fexp(ll) - fexp(SCALE * cs);
    }
}

// kernel 2: pipelined bf16 GEMM (16 warps) + fused w-norm + subcenter-max
// + partial sumexp + last-CTA inline finalize
__global__ void __launch_bounds__(THREADS, 1)
arc_main(const float* __restrict__ W, float* __restrict__ out){
    extern __shared__ char smem[];
    float* s_wsq = reinterpret_cast<float*>(smem + PIPE_BYTES);
    float* epi   = reinterpret_cast<float*>(smem);   // reuse pipeline smem after loop

    const int tid  = threadIdx.x;
    const int lane = tid & 31, warp = tid >> 5;
    const int g = lane >> 2, tg = lane & 3;
    const int wm = warp & 7, wn = warp >> 3;     // 8 M-warps x 2 N-warps, tile 32x48

    const int n0 = blockIdx.x * NT;

    float acc[2][6][4];
    #pragma unroll
    for (int a=0;a<2;a++)
      #pragma unroll
      for (int b=0;b<6;b++)
        #pragma unroll
        for (int c=0;c<4;c++) acc[a][b][c] = 0.0f;
    float bsq[6] = {0,0,0,0,0,0};

    const uint32_t smem_base = smem_u32(smem);

    auto issue = [&](int k0, int buf){
        uint32_t a_dst = smem_base + buf*STAGE_BYTES;
        uint32_t b_dst = smem_base + buf*STAGE_BYTES + A_STAGE_BYTES;
        const __nv_bfloat16* a_src = g_ebf + k0;
        const float*         b_src = W + (size_t)n0*EMBED + k0;
        #pragma unroll
        for (int p=0;p<4;p++){                 // A: 256 rows x 128B
            int idx = p*THREADS + tid;
            int r = idx >> 3, q = idx & 7;
            uint32_t d = a_dst + (uint32_t)(r*(SROW*2) + q*16);
            const void* s = a_src + (size_t)r*EMBED + q*8;
            asm volatile("cp.async.cg.shared.global [%0], [%1], 16;\n" :: "r"(d), "l"(s));
        }
        #pragma unroll
        for (int p=0;p<3;p++){                 // B: 96 rows x 256B (fp32)
            int idx = p*THREADS + tid;
            int r = idx >> 4, q = idx & 15;
            uint32_t d = b_dst + (uint32_t)(r*(SROWB*4) + q*16);
            const void* s = b_src + (size_t)r*EMBED + q*4;
            asm volatile("cp.async.cg.shared.global [%0], [%1], 16;\n" :: "r"(d), "l"(s));
        }
        asm volatile("cp.async.commit_group;\n");
    };

    auto mmachunk = [&](int buf){
        const __nv_bfloat16* Ab = reinterpret_cast<const __nv_bfloat16*>(smem + buf*STAGE_BYTES);
        const float*         Bb = reinterpret_cast<const float*>(smem + buf*STAGE_BYTES + A_STAGE_BYTES);
        #pragma unroll
        for (int kk=0; kk<4; kk++){
            const int kb = kk*16;
            uint32_t af[2][4];
            #pragma unroll
            for (int mt=0; mt<2; mt++){
                int r = wm*32 + mt*16 + (lane & 15);
                uint32_t addr = smem_u32(Ab + r*SROW + kb + (lane >> 4)*8);
                asm volatile("ldmatrix.sync.aligned.m8n8.x4.shared.b16 {%0,%1,%2,%3}, [%4];\n"
                             : "=r"(af[mt][0]), "=r"(af[mt][1]), "=r"(af[mt][2]), "=r"(af[mt][3])
                             : "r"(addr));
            }
            uint32_t bfr[6][2];
            #pragma unroll
            for (int nt=0; nt<6; nt++){
                int n = wn*48 + nt*8 + g;
                const float* bp = Bb + n*SROWB + kb + 2*tg;
                float2 v0 = *reinterpret_cast<const float2*>(bp);
                float2 v1 = *reinterpret_cast<const float2*>(bp + 8);
                if (wm == 0)
                    bsq[nt] += fmaf(v0.x,v0.x, fmaf(v0.y,v0.y, fmaf(v1.x,v1.x, v1.y*v1.y)));
                asm volatile("cvt.rn.bf16x2.f32 %0, %1, %2;\n" : "=r"(bfr[nt][0]) : "f"(v0.y), "f"(v0.x));
                asm volatile("cvt.rn.bf16x2.f32 %0, %1, %2;\n" : "=r"(bfr[nt][1]) : "f"(v1.y), "f"(v1.x));
            }
            #pragma unroll
            for (int mt=0; mt<2; mt++)
                #pragma unroll
                for (int nt=0; nt<6; nt++){
                    float* d = acc[mt][nt];
                    asm volatile(
                      "mma.sync.aligned.m16n8k16.row.col.f32.bf16.bf16.f32 "
                      "{%0,%1,%2,%3}, {%4,%5,%6,%7}, {%8,%9}, {%0,%1,%2,%3};\n"
                      : "+f"(d[0]), "+f"(d[1]), "+f"(d[2]), "+f"(d[3])
                      : "r"(af[mt][0]), "r"(af[mt][1]), "r"(af[mt][2]), "r"(af[mt][3]),
                        "r"(bfr[nt][0]), "r"(bfr[nt][1]));
                }
        }
    };

    // prologue: chunks 0, 1 in flight
    issue(0, 0);
    issue(KC, 1);

    #pragma unroll 1
    for (int kc=0; kc<CHUNKS; kc++){
        if (kc < CHUNKS-1) asm volatile("cp.async.wait_group 1;\n");
        else               asm volatile("cp.async.wait_group 0;\n");
        __syncthreads();                       // chunk kc ready; prior stage reads done
        if (kc + 2 < CHUNKS) issue((kc+2)*KC, (kc+2)%STAGES);
        mmachunk(kc % STAGES);
    }

    // per-row ||w||^2: wm==0 warps (0 and 8) hold full partials; reduce over tg
    if (wm == 0){
        #pragma unroll
        for (int nt=0; nt<6; nt++){
            float v = bsq[nt];
            v += __shfl_xor_sync(0xffffffffu, v, 1);
            v += __shfl_xor_sync(0xffffffffu, v, 2);
            if (tg == 0) s_wsq[wn*48 + nt*8 + g] = v;
        }
    }
    __syncthreads();
    if (tid < NT) s_wsq[tid] = rsqrtf(fmaxf(s_wsq[tid], 1e-24f));
    __syncthreads();   // all MMA/smem reads done; safe to reuse pipe smem as epi

    // scale by 1/||w|| and stage warp tile (32 rows x 48 cols) in smem
    float* my_epi = epi + (size_t)warp * (32 * EPI_STRIDE);
    #pragma unroll
    for (int mt=0; mt<2; mt++)
        #pragma unroll
        for (int nt=0; nt<6; nt++){
            int c0 = wn*48 + nt*8 + 2*tg;
            float i0 = s_wsq[c0], i1 = s_wsq[c0+1];
            int r0 = mt*16 + g;
            int cc = nt*8 + 2*tg;
            my_epi[ r0     *EPI_STRIDE + cc    ] = acc[mt][nt][0]*i0;
            my_epi[ r0     *EPI_STRIDE + cc + 1] = acc[mt][nt][1]*i1;
            my_epi[(r0 + 8)*EPI_STRIDE + cc    ] = acc[mt][nt][2]*i0;
            my_epi[(r0 + 8)*EPI_STRIDE + cc + 1] = acc[mt][nt][3]*i1;
        }
    __syncwarp();

    // each lane owns one row of the 32x48 warp tile: max3 + sumexp
    {
        float partial = 0.0f;
        #pragma unroll
        for (int c=0; c<16; c++){
            float v0 = my_epi[lane*EPI_STRIDE + c*3    ];
            float v1 = my_epi[lane*EPI_STRIDE + c*3 + 1];
            float v2 = my_epi[lane*EPI_STRIDE + c*3 + 2];
            float cs = fmaxf(v0, fmaxf(v1, v2));
            partial += fexp(SCALE * cs);
        }
        atomicAdd(&g_sumexp[wm*32 + lane], partial);
    }

    // ── inline finalize by the last CTA (atomic ticket) ──
    __threadfence();          // make this CTA's adds visible (release)
    __syncthreads();
    __shared__ unsigned int s_flag;
    if (tid == 0){
        unsigned int old = atomicAdd(&g_ticket, 1u);
        s_flag = (old == (unsigned)(NCTAS - 1)) ? 1u : 0u;
    }
    __syncthreads();
    if (s_flag){
        __threadfence();      // acquire
        float v = 0.0f;
        if (tid < BATCH){
            float S = __ldcg(&g_sumexp[tid]) + g_expadj[tid];
            v = logf(S) - g_lablogit[tid];
        }
        #pragma unroll
        for (int o=16;o;o>>=1) v += __shfl_xor_sync(0xffffffffu, v, o);
        float* ws = epi;      // smem scratch
        if ((tid & 31) == 0) ws[tid>>5] = v;
        __syncthreads();
        if (tid == 0){
            float s = 0.0f;
            #pragma unroll
            for (int i=0;i<8;i++) s += ws[i];
            out[0] = s * (1.0f/256.0f);
            g_ticket = 0;     // reset for next replay
        }
    }
}

extern "C" void kernel_launch(void* const* d_in, const int* in_sizes, int n_in,
                              void* d_out, int out_size){
    int ie = 0, il = 1, iw = 2;
    for (int i = 0; i < n_in; i++){
        if (in_sizes[i] == BATCH) il = i;
        else if (in_sizes[i] == BATCH*EMBED) ie = i;
        else if (in_sizes[i] == NSROWS*EMBED) iw = i;
    }
    const float* emb    = (const float*)d_in[ie];
    const void*  labels = (const void*)d_in[il];
    const float* W      = (const float*)d_in[iw];

    cudaFuncSetAttribute(arc_main, cudaFuncAttributeMaxDynamicSharedMemorySize, SMEM_BYTES);

    prep_label<<<320, 128>>>(emb, W, labels);
    arc_main<<<NCTAS, THREADS, SMEM_BYTES>>>(W, (float*)d_out);
}

// round 11
// speedup vs baseline: 1.0410x; 1.0410x over previous
#include <cuda_runtime.h>
#include <cuda_bf16.h>
#include <cstdint>

#define BATCH 256
#define EMBED 512
#define NCLS 100000
#define NSUB 3
#define NSROWS (NCLS*NSUB)

#define NT 96       // subcenter rows per CTA (= 32 classes)
#define KC 64       // K chunk
#define CHUNKS 8
#define STAGES 3
#define THREADS 512
#define NCTAS (NCLS/32)     // 3125
#define EPI_STRIDE 49

#define COSM 0.8775825618903728f
#define SINM 0.479425538604203f
#define THv (-0.8775825618903728f)
#define MMc 0.2397127693021015f
#define SCALE 64.0f

#define SROW 72         // A smem row stride (bf16 elems): 144B
#define SROWF 72        // B f32 stage row stride (words): 288B
#define SROWBB 72       // B bf16 tile row stride (elems): 144B
#define A_ST   (256*SROW*2)      // 36864
#define F32_ST (NT*SROWF*4)      // 27648
#define BB_ST  (NT*SROWBB*2)     // 13824
#define AOFF   0
#define F32OFF (STAGES*A_ST)               // 110592
#define BBOFF  (F32OFF + STAGES*F32_ST)    // 193536
#define WSQ_OFF (BBOFF + 2*BB_ST)          // 221184
#define SMEM_BYTES (WSQ_OFF + NT*4)        // 221568

__device__ __nv_bfloat16 g_ebf[BATCH*EMBED];
__device__ float g_sumexp[BATCH];
__device__ float g_lablogit[BATCH];
__device__ float g_expadj[BATCH];
__device__ unsigned int g_ticket;

// fast exp via FMA-pipe polynomial (avoid MUFU.EX2 throughput wall)
__device__ __forceinline__ float fexp(float x){
    float y = x * 1.4426950408889634f;
    int   n = __float2int_rn(y);
    float f = y - (float)n;
    float p = fmaf(f, 1.3333558e-3f, 9.6181291e-3f);
    p = fmaf(f, p, 5.5504109e-2f);
    p = fmaf(f, p, 2.4022651e-1f);
    p = fmaf(f, p, 6.9314718e-1f);
    p = fmaf(f, p, 1.0f);
    return p * __int_as_float((n + 127) << 23);
}

__device__ __forceinline__ uint32_t smem_u32(const void* p){
    return (uint32_t)__cvta_generic_to_shared(p);
}

// kernel 1 (fused): blocks 0..255 normalize embeddings -> bf16 scratch;
// blocks 256..319: exact fp32 label logits + sumexp correction (1 warp/row)
__global__ void prep_label(const float* __restrict__ emb,
                           const float* __restrict__ W,
                           const void*  __restrict__ labels_raw){
    if (blockIdx.x < 256){
        int row = blockIdx.x;
        int t = threadIdx.x;    // 128
        float4 v = reinterpret_cast<const float4*>(emb + (size_t)row*EMBED)[t];
        float ss = v.x*v.x + v.y*v.y + v.z*v.z + v.w*v.w;
        #pragma unroll
        for (int o=16;o;o>>=1) ss += __shfl_xor_sync(0xffffffffu, ss, o);
        __shared__ float wss[4];
        if ((t & 31) == 0) wss[t>>5] = ss;
        __syncthreads();
        float tot = wss[0]+wss[1]+wss[2]+wss[3];
        float inv = 1.0f / fmaxf(sqrtf(tot), 1e-12f);
        __nv_bfloat162 p0 = __float22bfloat162_rn(make_float2(v.x*inv, v.y*inv));
        __nv_bfloat162 p1 = __float22bfloat162_rn(make_float2(v.z*inv, v.w*inv));
        uint2 u;
        u.x = *reinterpret_cast<uint32_t*>(&p0);
        u.y = *reinterpret_cast<uint32_t*>(&p1);
        reinterpret_cast<uint2*>(g_ebf + (size_t)row*EMBED)[t] = u;
        if (t == 0) g_sumexp[row] = 0.0f;
        return;
    }
    int row  = (blockIdx.x - 256)*4 + (threadIdx.x >> 5);
    int lane = threadIdx.x & 31;

    const long long* l64 = (const long long*)labels_raw;
    const int*       l32 = (const int*)labels_raw;
    bool is64 = true;
    #pragma unroll
    for (int i=0;i<8;i++){
        long long v = l64[i];
        if (v < 0 || v >= (long long)NCLS) is64 = false;
    }
    long long lab = is64 ? l64[row] : (long long)l32[row];

    const float* e  = emb + (size_t)row*EMBED;
    const float* w0 = W   + (size_t)lab*NSUB*EMBED;

    float ess = 0.0f;
    float dot0=0.f, dot1=0.f, dot2=0.f;
    float ws0=0.f, ws1=0.f, ws2=0.f;
    for (int k = lane; k < EMBED; k += 32){
        float ev = e[k];
        ess = fmaf(ev, ev, ess);
        float a = w0[k];
        float b = w0[EMBED + k];
        float c = w0[2*EMBED + k];
        dot0 = fmaf(ev, a, dot0); ws0 = fmaf(a, a, ws0);
        dot1 = fmaf(ev, b, dot1); ws1 = fmaf(b, b, ws1);
        dot2 = fmaf(ev, c, dot2); ws2 = fmaf(c, c, ws2);
    }
    #pragma unroll
    for (int o=16;o;o>>=1){
        ess  += __shfl_xor_sync(0xffffffffu, ess,  o);
        dot0 += __shfl_xor_sync(0xffffffffu, dot0, o);
        dot1 += __shfl_xor_sync(0xffffffffu, dot1, o);
        dot2 += __shfl_xor_sync(0xffffffffu, dot2, o);
        ws0  += __shfl_xor_sync(0xffffffffu, ws0,  o);
        ws1  += __shfl_xor_sync(0xffffffffu, ws1,  o);
        ws2  += __shfl_xor_sync(0xffffffffu, ws2,  o);
    }
    if (lane == 0){
        float einv = 1.0f / fmaxf(sqrtf(ess), 1e-12f);
        float c0 = dot0 * einv / fmaxf(sqrtf(ws0), 1e-12f);
        float c1 = dot1 * einv / fmaxf(sqrtf(ws1), 1e-12f);
        float c2 = dot2 * einv / fmaxf(sqrtf(ws2), 1e-12f);
        float cs = fmaxf(c0, fmaxf(c1, c2));
        float sine = sqrtf(fmaxf(1.0f - cs*cs, 0.0f));
        float phi = (cs > THv) ? (cs*COSM - sine*SINM) : (cs - MMc);
        float ll = SCALE * phi;
        g_lablogit[row] = ll;
        g_expadj[row] = fexp(ll) - fexp(SCALE * cs);
    }
}

// kernel 2: pipelined bf16 GEMM, B converted once/chunk, all frags via ldmatrix
__global__ void __launch_bounds__(THREADS, 1)
arc_main(const float* __restrict__ W, float* __restrict__ out){
    extern __shared__ char smem[];
    float* s_wsq = reinterpret_cast<float*>(smem + WSQ_OFF);
    float* epi   = reinterpret_cast<float*>(smem);   // reuse pipeline smem after loop

    const int tid  = threadIdx.x;
    const int lane = tid & 31, warp = tid >> 5;
    const int g = lane >> 2, tg = lane & 3;
    const int wm = warp & 7, wn = warp >> 3;     // 8 M-warps x 2 N-warps, tile 32x48

    const int n0 = blockIdx.x * NT;

    float acc[2][6][4];
    #pragma unroll
    for (int a=0;a<2;a++)
      #pragma unroll
      for (int b=0;b<6;b++)
        #pragma unroll
        for (int c=0;c<4;c++) acc[a][b][c] = 0.0f;
    float bsq3[3] = {0.f, 0.f, 0.f};    // partial ||w||^2, row = p*32 + (tid>>4)

    const uint32_t smem_base = smem_u32(smem);

    auto issue = [&](int kc, int buf){
        uint32_t a_dst = smem_base + AOFF + buf*A_ST;
        uint32_t f_dst = smem_base + F32OFF + buf*F32_ST;
        const __nv_bfloat16* a_src = g_ebf + kc*KC;
        const float*         b_src = W + (size_t)n0*EMBED + kc*KC;
        #pragma unroll
        for (int p=0;p<4;p++){                 // A: 256 rows x 128B
            int idx = p*THREADS + tid;
            int r = idx >> 3, q = idx & 7;
            uint32_t d = a_dst + (uint32_t)(r*(SROW*2) + q*16);
            const void* s = a_src + (size_t)r*EMBED + q*8;
            asm volatile("cp.async.cg.shared.global [%0], [%1], 16;\n" :: "r"(d), "l"(s));
        }
        #pragma unroll
        for (int p=0;p<3;p++){                 // B: 96 rows x 256B (fp32)
            int idx = p*THREADS + tid;
            int r = idx >> 4, q = idx & 15;
            uint32_t d = f_dst + (uint32_t)(r*(SROWF*4) + q*16);
            const void* s = b_src + (size_t)r*EMBED + q*4;
            asm volatile("cp.async.cg.shared.global [%0], [%1], 16;\n" :: "r"(d), "l"(s));
        }
        asm volatile("cp.async.commit_group;\n");
    };

    // convert the fp32 B stage into a bf16 tile; accumulate ||w||^2 partials
    auto convert = [&](int sbuf, int bbuf){
        const float* Bf = reinterpret_cast<const float*>(smem + F32OFF + sbuf*F32_ST);
        char* Bb = smem + BBOFF + bbuf*BB_ST;
        #pragma unroll
        for (int p=0;p<3;p++){
            int idx = p*THREADS + tid;
            int r = idx >> 4, q = idx & 15;
            float4 v = *reinterpret_cast<const float4*>(Bf + r*SROWF + q*4);
            bsq3[p] += fmaf(v.x,v.x, fmaf(v.y,v.y, fmaf(v.z,v.z, v.w*v.w)));
            uint32_t lo, hi;
            asm volatile("cvt.rn.bf16x2.f32 %0, %1, %2;\n" : "=r"(lo) : "f"(v.y), "f"(v.x));
            asm volatile("cvt.rn.bf16x2.f32 %0, %1, %2;\n" : "=r"(hi) : "f"(v.w), "f"(v.z));
            *reinterpret_cast<uint2*>(Bb + r*(SROWBB*2) + q*8) = make_uint2(lo, hi);
        }
    };

    auto mmachunk = [&](int abuf, int bbuf){
        const __nv_bfloat16* Ab = reinterpret_cast<const __nv_bfloat16*>(smem + AOFF + abuf*A_ST);
        const char* Bb = smem + BBOFF + bbuf*BB_ST;
        #pragma unroll
        for (int kk=0; kk<4; kk++){
            const int kb = kk*16;                    // k offset in elems
            uint32_t af[2][4];
            #pragma unroll
            for (int mt=0; mt<2; mt++){
                int r = wm*32 + mt*16 + (lane & 15);
                uint32_t addr = smem_u32(Ab + r*SROW + kb + (lane >> 4)*8);
                asm volatile("ldmatrix.sync.aligned.m8n8.x4.shared.b16 {%0,%1,%2,%3}, [%4];\n"
                             : "=r"(af[mt][0]), "=r"(af[mt][1]), "=r"(af[mt][2]), "=r"(af[mt][3])
                             : "r"(addr));
            }
            uint32_t bfr[6][2];
            #pragma unroll
            for (int pr=0; pr<3; pr++){              // nt pair {2pr, 2pr+1}
                int grp = lane >> 3;
                int row = wn*48 + pr*16 + ((grp >> 1) << 3) + (lane & 7);
                uint32_t addr = smem_u32(Bb + row*(SROWBB*2) + kb*2 + (grp & 1)*16);
                asm volatile("ldmatrix.sync.aligned.m8n8.x4.shared.b16 {%0,%1,%2,%3}, [%4];\n"
                             : "=r"(bfr[2*pr][0]), "=r"(bfr[2*pr][1]),
                               "=r"(bfr[2*pr+1][0]), "=r"(bfr[2*pr+1][1])
                             : "r"(addr));
            }
            #pragma unroll
            for (int mt=0; mt<2; mt++)
                #pragma unroll
                for (int nt=0; nt<6; nt++){
                    float* d = acc[mt][nt];
                    asm volatile(
                      "mma.sync.aligned.m16n8k16.row.col.f32.bf16.bf16.f32 "
                      "{%0,%1,%2,%3}, {%4,%5,%6,%7}, {%8,%9}, {%0,%1,%2,%3};\n"
                      : "+f"(d[0]), "+f"(d[1]), "+f"(d[2]), "+f"(d[3])
                      : "r"(af[mt][0]), "r"(af[mt][1]), "r"(af[mt][2]), "r"(af[mt][3]),
                        "r"(bfr[nt][0]), "r"(bfr[nt][1]));
                }
        }
    };

    // prologue: chunks 0, 1 in flight
    issue(0, 0);
    issue(1, 1);

    #pragma unroll 1
    for (int kc=0; kc<CHUNKS; kc++){
        if (kc < CHUNKS-1) asm volatile("cp.async.wait_group 1;\n");
        else               asm volatile("cp.async.wait_group 0;\n");
        __syncthreads();                       // chunk kc staged; prior-chunk reads done
        if (kc + 2 < CHUNKS) issue(kc+2, (kc+2)%STAGES);
        convert(kc % STAGES, kc & 1);
        __syncthreads();                       // bf16 tile kc visible
        mmachunk(kc % STAGES, kc & 1);
    }

    // ||w||^2: reduce over the 16 lanes sharing a row, write s_wsq
    #pragma unroll
    for (int p=0;p<3;p++){
        float v = bsq3[p];
        v += __shfl_xor_sync(0xffffffffu, v, 1, 16);
        v += __shfl_xor_sync(0xffffffffu, v, 2, 16);
        v += __shfl_xor_sync(0xffffffffu, v, 4, 16);
        v += __shfl_xor_sync(0xffffffffu, v, 8, 16);
        if ((lane & 15) == 0) s_wsq[p*32 + (tid>>4)] = v;
    }
    __syncthreads();
    if (tid < NT) s_wsq[tid] = rsqrtf(fmaxf(s_wsq[tid], 1e-24f));
    __syncthreads();   // all MMA/smem reads done; safe to reuse pipe smem as epi

    // scale by 1/||w|| and stage warp tile (32 rows x 48 cols) in smem
    float* my_epi = epi + (size_t)warp * (32 * EPI_STRIDE);
    #pragma unroll
    for (int mt=0; mt<2; mt++)
        #pragma unroll
        for (int nt=0; nt<6; nt++){
            int c0 = wn*48 + nt*8 + 2*tg;
            float i0 = s_wsq[c0], i1 = s_wsq[c0+1];
            int r0 = mt*16 + g;
            int cc = nt*8 + 2*tg;
            my_epi[ r0     *EPI_STRIDE + cc    ] = acc[mt][nt][0]*i0;
            my_epi[ r0     *EPI_STRIDE + cc + 1] = acc[mt][nt][1]*i1;
            my_epi[(r0 + 8)*EPI_STRIDE + cc    ] = acc[mt][nt][2]*i0;
            my_epi[(r0 + 8)*EPI_STRIDE + cc + 1] = acc[mt][nt][3]*i1;
        }
    __syncwarp();

    // each lane owns one row of the 32x48 warp tile: max3 + sumexp
    {
        float partial = 0.0f;
        #pragma unroll
        for (int c=0; c<16; c++){
            float v0 = my_epi[lane*EPI_STRIDE + c*3    ];
            float v1 = my_epi[lane*EPI_STRIDE + c*3 + 1];
            float v2 = my_epi[lane*EPI_STRIDE + c*3 + 2];
            float cs = fmaxf(v0, fmaxf(v1, v2));
            partial += fexp(SCALE * cs);
        }
        atomicAdd(&g_sumexp[wm*32 + lane], partial);
    }

    // ── inline finalize by the last CTA (atomic ticket) ──
    __threadfence();
    __syncthreads();
    __shared__ unsigned int s_flag;
    if (tid == 0){
        unsigned int old = atomicAdd(&g_ticket, 1u);
        s_flag = (old == (unsigned)(NCTAS - 1)) ? 1u : 0u;
    }
    __syncthreads();
    if (s_flag){
        __threadfence();
        float v = 0.0f;
        if (tid < BATCH){
            float S = __ldcg(&g_sumexp[tid]) + g_expadj[tid];
            v = logf(S) - g_lablogit[tid];
        }
        #pragma unroll
        for (int o=16;o;o>>=1) v += __shfl_xor_sync(0xffffffffu, v, o);
        float* ws = epi;
        if ((tid & 31) == 0) ws[tid>>5] = v;
        __syncthreads();
        if (tid == 0){
            float s = 0.0f;
            #pragma unroll
            for (int i=0;i<8;i++) s += ws[i];
            out[0] = s * (1.0f/256.0f);
            g_ticket = 0;
        }
    }
}

extern "C" void kernel_launch(void* const* d_in, const int* in_sizes, int n_in,
                              void* d_out, int out_size){
    int ie = 0, il = 1, iw = 2;
    for (int i = 0; i < n_in; i++){
        if (in_sizes[i] == BATCH) il = i;
        else if (in_sizes[i] == BATCH*EMBED) ie = i;
        else if (in_sizes[i] == NSROWS*EMBED) iw = i;
    }
    const float* emb    = (const float*)d_in[ie];
    const void*  labels = (const void*)d_in[il];
    const float* W      = (const float*)d_in[iw];

    cudaFuncSetAttribute(arc_main, cudaFuncAttributeMaxDynamicSharedMemorySize, SMEM_BYTES);

    prep_label<<<320, 128>>>(emb, W, labels);
    arc_main<<<NCTAS, THREADS, SMEM_BYTES>>>(W, (float*)d_out);
}

// round 12
// speedup vs baseline: 1.1609x; 1.1152x over previous
#include <cuda_runtime.h>
#include <cuda_bf16.h>
#include <cstdint>

#define BATCH 256
#define EMBED 512
#define NCLS 100000
#define NSUB 3
#define NSROWS (NCLS*NSUB)

#define NT 96       // subcenter rows per CTA (= 32 classes)
#define KC 64       // K chunk
#define CHUNKS 8
#define THREADS 512
#define NCTAS (NCLS/32)     // 3125
#define EPI_STRIDE 49

#define COSM 0.8775825618903728f
#define SINM 0.479425538604203f
#define THv (-0.8775825618903728f)
#define MMc 0.2397127693021015f
#define SCALE 64.0f

// swizzled, unpadded tiles
#define A_ST   32768                 // 256 rows x 128B bf16, SW128
#define F_ST   24576                 // 96 rows x 256B fp32, linear
#define BB_ST  12288                 // 96 rows x 128B bf16, SW128
#define AOFF   0
#define FOFF   (4*A_ST)              // 131072  (A ring = 4)
#define BBOFF  (FOFF + 3*F_ST)       // 204800  (f32 ring = 3)
#define WSQ_OFF (BBOFF + 2*BB_ST)    // 229376  (bb ring = 2)
#define SMEM_BYTES (WSQ_OFF + 384)   // 229760

#define SW(o) ((o) ^ (((o) >> 3) & 0x70))

__device__ __nv_bfloat16 g_ebf[BATCH*EMBED];
__device__ float g_sumexp[BATCH];
__device__ float g_lablogit[BATCH];
__device__ float g_expadj[BATCH];
__device__ unsigned int g_ticket;

// fast exp via FMA-pipe polynomial (avoid MUFU.EX2 throughput wall)
__device__ __forceinline__ float fexp(float x){
    float y = x * 1.4426950408889634f;
    int   n = __float2int_rn(y);
    float f = y - (float)n;
    float p = fmaf(f, 1.3333558e-3f, 9.6181291e-3f);
    p = fmaf(f, p, 5.5504109e-2f);
    p = fmaf(f, p, 2.4022651e-1f);
    p = fmaf(f, p, 6.9314718e-1f);
    p = fmaf(f, p, 1.0f);
    return p * __int_as_float((n + 127) << 23);
}

__device__ __forceinline__ uint32_t smem_u32(const void* p){
    return (uint32_t)__cvta_generic_to_shared(p);
}

// kernel 1 (fused): blocks 0..255 normalize embeddings -> bf16 scratch;
// blocks 256..319: exact fp32 label logits + sumexp correction (1 warp/row)
__global__ void prep_label(const float* __restrict__ emb,
                           const float* __restrict__ W,
                           const void*  __restrict__ labels_raw){
    if (blockIdx.x < 256){
        int row = blockIdx.x;
        int t = threadIdx.x;    // 128
        float4 v = reinterpret_cast<const float4*>(emb + (size_t)row*EMBED)[t];
        float ss = v.x*v.x + v.y*v.y + v.z*v.z + v.w*v.w;
        #pragma unroll
        for (int o=16;o;o>>=1) ss += __shfl_xor_sync(0xffffffffu, ss, o);
        __shared__ float wss[4];
        if ((t & 31) == 0) wss[t>>5] = ss;
        __syncthreads();
        float tot = wss[0]+wss[1]+wss[2]+wss[3];
        float inv = 1.0f / fmaxf(sqrtf(tot), 1e-12f);
        __nv_bfloat162 p0 = __float22bfloat162_rn(make_float2(v.x*inv, v.y*inv));
        __nv_bfloat162 p1 = __float22bfloat162_rn(make_float2(v.z*inv, v.w*inv));
        uint2 u;
        u.x = *reinterpret_cast<uint32_t*>(&p0);
        u.y = *reinterpret_cast<uint32_t*>(&p1);
        reinterpret_cast<uint2*>(g_ebf + (size_t)row*EMBED)[t] = u;
        if (t == 0) g_sumexp[row] = 0.0f;
        return;
    }
    int row  = (blockIdx.x - 256)*4 + (threadIdx.x >> 5);
    int lane = threadIdx.x & 31;

    const long long* l64 = (const long long*)labels_raw;
    const int*       l32 = (const int*)labels_raw;
    bool is64 = true;
    #pragma unroll
    for (int i=0;i<8;i++){
        long long v = l64[i];
        if (v < 0 || v >= (long long)NCLS) is64 = false;
    }
    long long lab = is64 ? l64[row] : (long long)l32[row];

    const float* e  = emb + (size_t)row*EMBED;
    const float* w0 = W   + (size_t)lab*NSUB*EMBED;

    float ess = 0.0f;
    float dot0=0.f, dot1=0.f, dot2=0.f;
    float ws0=0.f, ws1=0.f, ws2=0.f;
    for (int k = lane; k < EMBED; k += 32){
        float ev = e[k];
        ess = fmaf(ev, ev, ess);
        float a = w0[k];
        float b = w0[EMBED + k];
        float c = w0[2*EMBED + k];
        dot0 = fmaf(ev, a, dot0); ws0 = fmaf(a, a, ws0);
        dot1 = fmaf(ev, b, dot1); ws1 = fmaf(b, b, ws1);
        dot2 = fmaf(ev, c, dot2); ws2 = fmaf(c, c, ws2);
    }
    #pragma unroll
    for (int o=16;o;o>>=1){
        ess  += __shfl_xor_sync(0xffffffffu, ess,  o);
        dot0 += __shfl_xor_sync(0xffffffffu, dot0, o);
        dot1 += __shfl_xor_sync(0xffffffffu, dot1, o);
        dot2 += __shfl_xor_sync(0xffffffffu, dot2, o);
        ws0  += __shfl_xor_sync(0xffffffffu, ws0,  o);
        ws1  += __shfl_xor_sync(0xffffffffu, ws1,  o);
        ws2  += __shfl_xor_sync(0xffffffffu, ws2,  o);
    }
    if (lane == 0){
        float einv = 1.0f / fmaxf(sqrtf(ess), 1e-12f);
        float c0 = dot0 * einv / fmaxf(sqrtf(ws0), 1e-12f);
        float c1 = dot1 * einv / fmaxf(sqrtf(ws1), 1e-12f);
        float c2 = dot2 * einv / fmaxf(sqrtf(ws2), 1e-12f);
        float cs = fmaxf(c0, fmaxf(c1, c2));
        float sine = sqrtf(fmaxf(1.0f - cs*cs, 0.0f));
        float phi = (cs > THv) ? (cs*COSM - sine*SINM) : (cs - MMc);
        float ll = SCALE * phi;
        g_lablogit[row] = ll;
        g_expadj[row] = fexp(ll) - fexp(SCALE * cs);
    }
}

// kernel 2: single-barrier-per-chunk pipelined bf16 GEMM
// epoch kc: [issue(kc+2) | wait | SYNC | convert(kc+1) + mma(kc)]
__global__ void __launch_bounds__(THREADS, 1)
arc_main(const float* __restrict__ W, float* __restrict__ out){
    extern __shared__ char smem[];
    float* s_wsq = reinterpret_cast<float*>(smem + WSQ_OFF);
    float* epi   = reinterpret_cast<float*>(smem);   // reuse pipeline smem after loop

    const int tid  = threadIdx.x;
    const int lane = tid & 31, warp = tid >> 5;
    const int g = lane >> 2, tg = lane & 3;
    const int wm = warp & 7, wn = warp >> 3;     // 8 M-warps x 2 N-warps, tile 32x48

    const int n0 = blockIdx.x * NT;

    float acc[2][6][4];
    #pragma unroll
    for (int a=0;a<2;a++)
      #pragma unroll
      for (int b=0;b<6;b++)
        #pragma unroll
        for (int c=0;c<4;c++) acc[a][b][c] = 0.0f;
    float bsq3[3] = {0.f, 0.f, 0.f};    // partial ||w||^2, row = p*32 + (tid>>4)

    const uint32_t smem_base = smem_u32(smem);

    auto issue = [&](int kc){
        uint32_t a_dst = smem_base + AOFF + (kc & 3)*A_ST;
        uint32_t f_dst = smem_base + FOFF + (kc % 3)*F_ST;
        const __nv_bfloat16* a_src = g_ebf + kc*KC;
        const float*         b_src = W + (size_t)n0*EMBED + kc*KC;
        #pragma unroll
        for (int p=0;p<4;p++){                 // A: 256 rows x 128B, swizzled
            int idx = p*THREADS + tid;
            int r = idx >> 3, q = idx & 7;
            uint32_t o = (uint32_t)(r*128 + q*16);
            uint32_t d = a_dst + SW(o);
            const void* s = a_src + (size_t)r*EMBED + q*8;
            asm volatile("cp.async.cg.shared.global [%0], [%1], 16;\n" :: "r"(d), "l"(s));
        }
        #pragma unroll
        for (int p=0;p<3;p++){                 // B: 96 rows x 256B fp32, linear
            int idx = p*THREADS + tid;
            int r = idx >> 4, q = idx & 15;
            uint32_t d = f_dst + (uint32_t)(r*256 + q*16);
            const void* s = b_src + (size_t)r*EMBED + q*4;
            asm volatile("cp.async.cg.shared.global [%0], [%1], 16;\n" :: "r"(d), "l"(s));
        }
        asm volatile("cp.async.commit_group;\n");
    };

    // convert fp32 B stage -> swizzled bf16 tile; accumulate ||w||^2 partials
    auto convert = [&](int kc){
        const float* Bf = reinterpret_cast<const float*>(smem + FOFF + (kc % 3)*F_ST);
        char* Bb = smem + BBOFF + (kc & 1)*BB_ST;
        #pragma unroll
        for (int p=0;p<3;p++){
            int idx = p*THREADS + tid;
            int r = idx >> 4, q = idx & 15;
            float4 v = *reinterpret_cast<const float4*>(Bf + r*64 + q*4);
            bsq3[p] += fmaf(v.x,v.x, fmaf(v.y,v.y, fmaf(v.z,v.z, v.w*v.w)));
            uint32_t lo, hi;
            asm volatile("cvt.rn.bf16x2.f32 %0, %1, %2;\n" : "=r"(lo) : "f"(v.y), "f"(v.x));
            asm volatile("cvt.rn.bf16x2.f32 %0, %1, %2;\n" : "=r"(hi) : "f"(v.w), "f"(v.z));
            uint32_t o = (uint32_t)(r*128 + q*8);
            *reinterpret_cast<uint2*>(Bb + SW(o)) = make_uint2(lo, hi);
        }
    };

    auto mmachunk = [&](int kc){
        const char* Ab = smem + AOFF + (kc & 3)*A_ST;
        const char* Bb = smem + BBOFF + (kc & 1)*BB_ST;
        #pragma unroll
        for (int kk=0; kk<4; kk++){
            uint32_t af[2][4];
            #pragma unroll
            for (int mt=0; mt<2; mt++){
                int r = wm*32 + mt*16 + (lane & 15);
                uint32_t o = (uint32_t)(r*128 + kk*32 + (lane >> 4)*16);
                uint32_t addr = smem_u32(Ab) + SW(o);
                asm volatile("ldmatrix.sync.aligned.m8n8.x4.shared.b16 {%0,%1,%2,%3}, [%4];\n"
                             : "=r"(af[mt][0]), "=r"(af[mt][1]), "=r"(af[mt][2]), "=r"(af[mt][3])
                             : "r"(addr));
            }
            uint32_t bfr[6][2];
            #pragma unroll
            for (int pr=0; pr<3; pr++){              // nt pair {2pr, 2pr+1}
                int grp = lane >> 3;
                int row = wn*48 + pr*16 + ((grp >> 1) << 3) + (lane & 7);
                uint32_t o = (uint32_t)(row*128 + kk*32 + (grp & 1)*16);
                uint32_t addr = smem_u32(Bb) + SW(o);
                asm volatile("ldmatrix.sync.aligned.m8n8.x4.shared.b16 {%0,%1,%2,%3}, [%4];\n"
                             : "=r"(bfr[2*pr][0]), "=r"(bfr[2*pr][1]),
                               "=r"(bfr[2*pr+1][0]), "=r"(bfr[2*pr+1][1])
                             : "r"(addr));
            }
            #pragma unroll
            for (int mt=0; mt<2; mt++)
                #pragma unroll
                for (int nt=0; nt<6; nt++){
                    float* d = acc[mt][nt];
                    asm volatile(
                      "mma.sync.aligned.m16n8k16.row.col.f32.bf16.bf16.f32 "
                      "{%0,%1,%2,%3}, {%4,%5,%6,%7}, {%8,%9}, {%0,%1,%2,%3};\n"
                      : "+f"(d[0]), "+f"(d[1]), "+f"(d[2]), "+f"(d[3])
                      : "r"(af[mt][0]), "r"(af[mt][1]), "r"(af[mt][2]), "r"(af[mt][3]),
                        "r"(bfr[nt][0]), "r"(bfr[nt][1]));
                }
        }
    };

    // prologue: chunks 0,1 in flight; convert chunk 0
    issue(0);
    issue(1);
    asm volatile("cp.async.wait_group 1;\n");
    __syncthreads();
    convert(0);

    #pragma unroll 1
    for (int kc=0; kc<CHUNKS; kc++){
        if (kc + 2 < CHUNKS) issue(kc+2);
        if (kc + 1 < CHUNKS){
            if (kc + 2 < CHUNKS) asm volatile("cp.async.wait_group 1;\n");
            else                 asm volatile("cp.async.wait_group 0;\n");
        }
        __syncthreads();      // chunk kc+1 staged visible; bb[kc&1] visible; prior reads done
        if (kc + 1 < CHUNKS) convert(kc+1);
        mmachunk(kc);
    }

    // ||w||^2: reduce over the 16 lanes sharing a row, write s_wsq
    #pragma unroll
    for (int p=0;p<3;p++){
        float v = bsq3[p];
        v += __shfl_xor_sync(0xffffffffu, v, 1, 16);
        v += __shfl_xor_sync(0xffffffffu, v, 2, 16);
        v += __shfl_xor_sync(0xffffffffu, v, 4, 16);
        v += __shfl_xor_sync(0xffffffffu, v, 8, 16);
        if ((lane & 15) == 0) s_wsq[p*32 + (tid>>4)] = v;
    }
    __syncthreads();
    if (tid < NT) s_wsq[tid] = rsqrtf(fmaxf(s_wsq[tid], 1e-24f));
    __syncthreads();   // all MMA/smem reads done; safe to reuse pipe smem as epi

    // scale by 1/||w|| and stage warp tile (32 rows x 48 cols) in smem
    float* my_epi = epi + (size_t)warp * (32 * EPI_STRIDE);
    #pragma unroll
    for (int mt=0; mt<2; mt++)
        #pragma unroll
        for (int nt=0; nt<6; nt++){
            int c0 = wn*48 + nt*8 + 2*tg;
            float i0 = s_wsq[c0], i1 = s_wsq[c0+1];
            int r0 = mt*16 + g;
            int cc = nt*8 + 2*tg;
            my_epi[ r0     *EPI_STRIDE + cc    ] = acc[mt][nt][0]*i0;
            my_epi[ r0     *EPI_STRIDE + cc + 1] = acc[mt][nt][1]*i1;
            my_epi[(r0 + 8)*EPI_STRIDE + cc    ] = acc[mt][nt][2]*i0;
            my_epi[(r0 + 8)*EPI_STRIDE + cc + 1] = acc[mt][nt][3]*i1;
        }
    __syncwarp();

    // each lane owns one row of the 32x48 warp tile: max3 + sumexp
    {
        float partial = 0.0f;
        #pragma unroll
        for (int c=0; c<16; c++){
            float v0 = my_epi[lane*EPI_STRIDE + c*3    ];
            float v1 = my_epi[lane*EPI_STRIDE + c*3 + 1];
            float v2 = my_epi[lane*EPI_STRIDE + c*3 + 2];
            float cs = fmaxf(v0, fmaxf(v1, v2));
            partial += fexp(SCALE * cs);
        }
        atomicAdd(&g_sumexp[wm*32 + lane], partial);
    }

    // ── inline finalize by the last CTA (atomic ticket) ──
    __threadfence();
    __syncthreads();
    __shared__ unsigned int s_flag;
    if (tid == 0){
        unsigned int old = atomicAdd(&g_ticket, 1u);
        s_flag = (old == (unsigned)(NCTAS - 1)) ? 1u : 0u;
    }
    __syncthreads();
    if (s_flag){
        __threadfence();
        float v = 0.0f;
        if (tid < BATCH){
            float S = __ldcg(&g_sumexp[tid]) + g_expadj[tid];
            v = logf(S) - g_lablogit[tid];
        }
        #pragma unroll
        for (int o=16;o;o>>=1) v += __shfl_xor_sync(0xffffffffu, v, o);
        float* ws = epi;
        if ((tid & 31) == 0) ws[tid>>5] = v;
        __syncthreads();
        if (tid == 0){
            float s = 0.0f;
            #pragma unroll
            for (int i=0;i<8;i++) s += ws[i];
            out[0] = s * (1.0f/256.0f);
            g_ticket = 0;
        }
    }
}

extern "C" void kernel_launch(void* const* d_in, const int* in_sizes, int n_in,
                              void* d_out, int out_size){
    int ie = 0, il = 1, iw = 2;
    for (int i = 0; i < n_in; i++){
        if (in_sizes[i] == BATCH) il = i;
        else if (in_sizes[i] == BATCH*EMBED) ie = i;
        else if (in_sizes[i] == NSROWS*EMBED) iw = i;
    }
    const float* emb    = (const float*)d_in[ie];
    const void*  labels = (const void*)d_in[il];
    const float* W      = (const float*)d_in[iw];

    cudaFuncSetAttribute(arc_main, cudaFuncAttributeMaxDynamicSharedMemorySize, SMEM_BYTES);

    prep_label<<<320, 128>>>(emb, W, labels);
    arc_main<<<NCTAS, THREADS, SMEM_BYTES>>>(W, (float*)d_out);
}

// round 14
// speedup vs baseline: 1.3369x; 1.1516x over previous
#include <cuda_runtime.h>
#include <cuda_bf16.h>
#include <cstdint>

#define BATCH 256
#define EMBED 512
#define NCLS 100000
#define NSUB 3
#define NSROWS (NCLS*NSUB)

#define NT 96       // subcenter rows per CTA (= 32 classes)
#define KC 64       // K chunk
#define CHUNKS 8
#define THREADS 512
#define NCTAS (NCLS/32)     // 3125
#define EPI_STRIDE 49

#define COSM 0.8775825618903728f
#define SINM 0.479425538604203f
#define THv (-0.8775825618903728f)
#define MMc 0.2397127693021015f
#define SCALE 64.0f

// swizzled, unpadded tiles
#define A_ST   32768                 // 256 rows x 128B bf16, SW128
#define BB_ST  12288                 // 96 rows x 128B bf16, SW128
#define AOFF   0
#define BBOFF  (4*A_ST)              // 131072  (A ring = 4)
#define WSQ_OFF (BBOFF + 2*BB_ST)    // 155648  (bb ring = 2)
#define SMEM_BYTES (WSQ_OFF + 384)   // 156032

#define SW(o) ((o) ^ (((o) >> 3) & 0x70))

__device__ __nv_bfloat16 g_ebf[BATCH*EMBED];
__device__ float g_sumexp[BATCH];
__device__ float g_lablogit[BATCH];
__device__ float g_expadj[BATCH];
__device__ unsigned int g_ticket;

// fast exp via FMA-pipe polynomial (avoid MUFU.EX2 throughput wall)
__device__ __forceinline__ float fexp(float x){
    float y = x * 1.4426950408889634f;
    int   n = __float2int_rn(y);
    float f = y - (float)n;
    float p = fmaf(f, 1.3333558e-3f, 9.6181291e-3f);
    p = fmaf(f, p, 5.5504109e-2f);
    p = fmaf(f, p, 2.4022651e-1f);
    p = fmaf(f, p, 6.9314718e-1f);
    p = fmaf(f, p, 1.0f);
    return p * __int_as_float((n + 127) << 23);
}

__device__ __forceinline__ uint32_t smem_u32(const void* p){
    return (uint32_t)__cvta_generic_to_shared(p);
}

// kernel 1 (fused): blocks 0..255 normalize embeddings -> bf16 scratch;
// blocks 256..319: exact fp32 label logits + sumexp correction (1 warp/row)
__global__ void prep_label(const float* __restrict__ emb,
                           const float* __restrict__ W,
                           const void*  __restrict__ labels_raw){
    if (blockIdx.x < 256){
        int row = blockIdx.x;
        int t = threadIdx.x;    // 128
        float4 v = reinterpret_cast<const float4*>(emb + (size_t)row*EMBED)[t];
        float ss = v.x*v.x + v.y*v.y + v.z*v.z + v.w*v.w;
        #pragma unroll
        for (int o=16;o;o>>=1) ss += __shfl_xor_sync(0xffffffffu, ss, o);
        __shared__ float wss[4];
        if ((t & 31) == 0) wss[t>>5] = ss;
        __syncthreads();
        float tot = wss[0]+wss[1]+wss[2]+wss[3];
        float inv = 1.0f / fmaxf(sqrtf(tot), 1e-12f);
        __nv_bfloat162 p0 = __float22bfloat162_rn(make_float2(v.x*inv, v.y*inv));
        __nv_bfloat162 p1 = __float22bfloat162_rn(make_float2(v.z*inv, v.w*inv));
        uint2 u;
        u.x = *reinterpret_cast<uint32_t*>(&p0);
        u.y = *reinterpret_cast<uint32_t*>(&p1);
        reinterpret_cast<uint2*>(g_ebf + (size_t)row*EMBED)[t] = u;
        if (t == 0) g_sumexp[row] = 0.0f;
        return;
    }
    int row  = (blockIdx.x - 256)*4 + (threadIdx.x >> 5);
    int lane = threadIdx.x & 31;

    const long long* l64 = (const long long*)labels_raw;
    const int*       l32 = (const int*)labels_raw;
    bool is64 = true;
    #pragma unroll
    for (int i=0;i<8;i++){
        long long v = l64[i];
        if (v < 0 || v >= (long long)NCLS) is64 = false;
    }
    long long lab = is64 ? l64[row] : (long long)l32[row];

    const float* e  = emb + (size_t)row*EMBED;
    const float* w0 = W   + (size_t)lab*NSUB*EMBED;

    float ess = 0.0f;
    float dot0=0.f, dot1=0.f, dot2=0.f;
    float ws0=0.f, ws1=0.f, ws2=0.f;
    for (int k = lane; k < EMBED; k += 32){
        float ev = e[k];
        ess = fmaf(ev, ev, ess);
        float a = w0[k];
        float b = w0[EMBED + k];
        float c = w0[2*EMBED + k];
        dot0 = fmaf(ev, a, dot0); ws0 = fmaf(a, a, ws0);
        dot1 = fmaf(ev, b, dot1); ws1 = fmaf(b, b, ws1);
        dot2 = fmaf(ev, c, dot2); ws2 = fmaf(c, c, ws2);
    }
    #pragma unroll
    for (int o=16;o;o>>=1){
        ess  += __shfl_xor_sync(0xffffffffu, ess,  o);
        dot0 += __shfl_xor_sync(0xffffffffu, dot0, o);
        dot1 += __shfl_xor_sync(0xffffffffu, dot1, o);
        dot2 += __shfl_xor_sync(0xffffffffu, dot2, o);
        ws0  += __shfl_xor_sync(0xffffffffu, ws0,  o);
        ws1  += __shfl_xor_sync(0xffffffffu, ws1,  o);
        ws2  += __shfl_xor_sync(0xffffffffu, ws2,  o);
    }
    if (lane == 0){
        float einv = 1.0f / fmaxf(sqrtf(ess), 1e-12f);
        float c0 = dot0 * einv / fmaxf(sqrtf(ws0), 1e-12f);
        float c1 = dot1 * einv / fmaxf(sqrtf(ws1), 1e-12f);
        float c2 = dot2 * einv / fmaxf(sqrtf(ws2), 1e-12f);
        float cs = fmaxf(c0, fmaxf(c1, c2));
        float sine = sqrtf(fmaxf(1.0f - cs*cs, 0.0f));
        float phi = (cs > THv) ? (cs*COSM - sine*SINM) : (cs - MMc);
        float ll = SCALE * phi;
        g_lablogit[row] = ll;
        g_expadj[row] = fexp(ll) - fexp(SCALE * cs);
    }
}

// kernel 2: single-barrier-per-chunk pipelined bf16 GEMM, B staged via LDG->regs
// epoch kc: [issueA(kc+2) | ldgB(kc+1) | wait | SYNC | mma(kc) | cvt+STS bb(kc+1)]
__global__ void __launch_bounds__(THREADS, 1)
arc_main(const float* __restrict__ W, float* __restrict__ out){
    extern __shared__ char smem[];
    float* s_wsq = reinterpret_cast<float*>(smem + WSQ_OFF);
    float* epi   = reinterpret_cast<float*>(smem);   // reuse pipeline smem after loop

    const int tid  = threadIdx.x;
    const int lane = tid & 31, warp = tid >> 5;
    const int g = lane >> 2, tg = lane & 3;
    const int wm = warp & 7, wn = warp >> 3;     // 8 M-warps x 2 N-warps, tile 32x48

    const int n0 = blockIdx.x * NT;

    float acc[2][6][4];
    #pragma unroll
    for (int a=0;a<2;a++)
      #pragma unroll
      for (int b=0;b<6;b++)
        #pragma unroll
        for (int c=0;c<4;c++) acc[a][b][c] = 0.0f;
    float bsq3[3] = {0.f, 0.f, 0.f};    // partial ||w||^2, row = p*32 + (tid>>4)

    const uint32_t smem_base = smem_u32(smem);
    // per-thread B panel mapping: p in 0..2, idx = p*512+tid, r = idx>>4, q = idx&15
    const int br = tid >> 4;            // row for p=0 (p adds 32)
    const int bq = tid & 15;            // quad column (4 floats)
    const float* Wbase = W + (size_t)n0*EMBED;

    float4 sB[3];                        // LDG staging for one chunk

    auto issueA = [&](int kc){
        uint32_t a_dst = smem_base + AOFF + (kc & 3)*A_ST;
        const __nv_bfloat16* a_src = g_ebf + kc*KC;
        #pragma unroll
        for (int p=0;p<4;p++){                 // A: 256 rows x 128B, swizzled
            int idx = p*THREADS + tid;
            int r = idx >> 3, q = idx & 7;
            uint32_t o = (uint32_t)(r*128 + q*16);
            uint32_t d = a_dst + SW(o);
            const void* s = a_src + (size_t)r*EMBED + q*8;
            asm volatile("cp.async.cg.shared.global [%0], [%1], 16;\n" :: "r"(d), "l"(s));
        }
        asm volatile("cp.async.commit_group;\n");
    };

    auto ldgB = [&](int kc){
        const float* src = Wbase + kc*KC;
        #pragma unroll
        for (int p=0;p<3;p++)
            sB[p] = *reinterpret_cast<const float4*>(src + (size_t)(br + p*32)*EMBED + bq*4);
    };

    // cvt staged regs -> swizzled bf16 tile; accumulate ||w||^2 partials
    auto cvtStoreB = [&](int kc){
        char* Bb = smem + BBOFF + (kc & 1)*BB_ST;
        #pragma unroll
        for (int p=0;p<3;p++){
            float4 v = sB[p];
            bsq3[p] += fmaf(v.x,v.x, fmaf(v.y,v.y, fmaf(v.z,v.z, v.w*v.w)));
            uint32_t lo, hi;
            asm volatile("cvt.rn.bf16x2.f32 %0, %1, %2;\n" : "=r"(lo) : "f"(v.y), "f"(v.x));
            asm volatile("cvt.rn.bf16x2.f32 %0, %1, %2;\n" : "=r"(hi) : "f"(v.w), "f"(v.z));
            uint32_t o = (uint32_t)((br + p*32)*128 + bq*8);
            *reinterpret_cast<uint2*>(Bb + SW(o)) = make_uint2(lo, hi);
        }
    };

    auto mmachunk = [&](int kc){
        const char* Ab = smem + AOFF + (kc & 3)*A_ST;
        const char* Bb = smem + BBOFF + (kc & 1)*BB_ST;
        #pragma unroll
        for (int kk=0; kk<4; kk++){
            uint32_t af[2][4];
            #pragma unroll
            for (int mt=0; mt<2; mt++){
                int r = wm*32 + mt*16 + (lane & 15);
                uint32_t o = (uint32_t)(r*128 + kk*32 + (lane >> 4)*16);
                uint32_t addr = smem_u32(Ab) + SW(o);
                asm volatile("ldmatrix.sync.aligned.m8n8.x4.shared.b16 {%0,%1,%2,%3}, [%4];\n"
                             : "=r"(af[mt][0]), "=r"(af[mt][1]), "=r"(af[mt][2]), "=r"(af[mt][3])
                             : "r"(addr));
            }
            uint32_t bfr[6][2];
            #pragma unroll
            for (int pr=0; pr<3; pr++){              // nt pair {2pr, 2pr+1}
                int grp = lane >> 3;
                int row = wn*48 + pr*16 + ((grp >> 1) << 3) + (lane & 7);
                uint32_t o = (uint32_t)(row*128 + kk*32 + (grp & 1)*16);
                uint32_t addr = smem_u32(Bb) + SW(o);
                asm volatile("ldmatrix.sync.aligned.m8n8.x4.shared.b16 {%0,%1,%2,%3}, [%4];\n"
                             : "=r"(bfr[2*pr][0]), "=r"(bfr[2*pr][1]),
                               "=r"(bfr[2*pr+1][0]), "=r"(bfr[2*pr+1][1])
                             : "r"(addr));
            }
            #pragma unroll
            for (int mt=0; mt<2; mt++)
                #pragma unroll
                for (int nt=0; nt<6; nt++){
                    float* d = acc[mt][nt];
                    asm volatile(
                      "mma.sync.aligned.m16n8k16.row.col.f32.bf16.bf16.f32 "
                      "{%0,%1,%2,%3}, {%4,%5,%6,%7}, {%8,%9}, {%0,%1,%2,%3};\n"
                      : "+f"(d[0]), "+f"(d[1]), "+f"(d[2]), "+f"(d[3])
                      : "r"(af[mt][0]), "r"(af[mt][1]), "r"(af[mt][2]), "r"(af[mt][3]),
                        "r"(bfr[nt][0]), "r"(bfr[nt][1]));
                }
        }
    };

    // prologue: A chunks 0,1 in flight; B chunk 0 converted
    issueA(0);
    issueA(1);
    ldgB(0);
    cvtStoreB(0);

    #pragma unroll 1
    for (int kc=0; kc<CHUNKS; kc++){
        if (kc + 2 < CHUNKS) issueA(kc+2);
        if (kc + 1 < CHUNKS) ldgB(kc+1);
        if (kc + 2 < CHUNKS)      asm volatile("cp.async.wait_group 2;\n");
        else if (kc + 1 < CHUNKS) asm volatile("cp.async.wait_group 1;\n");
        else                      asm volatile("cp.async.wait_group 0;\n");
        __syncthreads();      // A(kc) + bb(kc) visible; prior-chunk reads done
        mmachunk(kc);
        if (kc + 1 < CHUNKS) cvtStoreB(kc+1);
    }

    // ||w||^2: reduce over the 16 lanes sharing a row, write s_wsq
    #pragma unroll
    for (int p=0;p<3;p++){
        float v = bsq3[p];
        v += __shfl_xor_sync(0xffffffffu, v, 1, 16);
        v += __shfl_xor_sync(0xffffffffu, v, 2, 16);
        v += __shfl_xor_sync(0xffffffffu, v, 4, 16);
        v += __shfl_xor_sync(0xffffffffu, v, 8, 16);
        if ((lane & 15) == 0) s_wsq[p*32 + (tid>>4)] = v;
    }
    __syncthreads();
    if (tid < NT) s_wsq[tid] = rsqrtf(fmaxf(s_wsq[tid], 1e-24f));
    __syncthreads();   // all MMA/smem reads done; safe to reuse pipe smem as epi

    // scale by 1/||w|| and stage warp tile (32 rows x 48 cols) in smem
    float* my_epi = epi + (size_t)warp * (32 * EPI_STRIDE);
    #pragma unroll
    for (int mt=0; mt<2; mt++)
        #pragma unroll
        for (int nt=0; nt<6; nt++){
            int c0 = wn*48 + nt*8 + 2*tg;
            float i0 = s_wsq[c0], i1 = s_wsq[c0+1];
            int r0 = mt*16 + g;
            int cc = nt*8 + 2*tg;
            my_epi[ r0     *EPI_STRIDE + cc    ] = acc[mt][nt][0]*i0;
            my_epi[ r0     *EPI_STRIDE + cc + 1] = acc[mt][nt][1]*i1;
            my_epi[(r0 + 8)*EPI_STRIDE + cc    ] = acc[mt][nt][2]*i0;
            my_epi[(r0 + 8)*EPI_STRIDE + cc + 1] = acc[mt][nt][3]*i1;
        }
    __syncwarp();

    // each lane owns one row of the 32x48 warp tile: max3 + sumexp
    {
        float partial = 0.0f;
        #pragma unroll
        for (int c=0; c<16; c++){
            float v0 = my_epi[lane*EPI_STRIDE + c*3    ];
            float v1 = my_epi[lane*EPI_STRIDE + c*3 + 1];
            float v2 = my_epi[lane*EPI_STRIDE + c*3 + 2];
            float cs = fmaxf(v0, fmaxf(v1, v2));
            partial += fexp(SCALE * cs);
        }
        atomicAdd(&g_sumexp[wm*32 + lane], partial);
    }

    // ── inline finalize by the last CTA (atomic ticket) ──
    __threadfence();
    __syncthreads();
    __shared__ unsigned int s_flag;
    if (tid == 0){
        unsigned int old = atomicAdd(&g_ticket, 1u);
        s_flag = (old == (unsigned)(NCTAS - 1)) ? 1u : 0u;
    }
    __syncthreads();
    if (s_flag){
        __threadfence();
        float v = 0.0f;
        if (tid < BATCH){
            float S = __ldcg(&g_sumexp[tid]) + g_expadj[tid];
            v = logf(S) - g_lablogit[tid];
        }
        #pragma unroll
        for (int o=16;o;o>>=1) v += __shfl_xor_sync(0xffffffffu, v, o);
        float* ws = epi;
        if ((tid & 31) == 0) ws[tid>>5] = v;
        __syncthreads();
        if (tid == 0){
            float s = 0.0f;
            #pragma unroll
            for (int i=0;i<8;i++) s += ws[i];
            out[0] = s * (1.0f/256.0f);
            g_ticket = 0;
        }
    }
}

extern "C" void kernel_launch(void* const* d_in, const int* in_sizes, int n_in,
                              void* d_out, int out_size){
    int ie = 0, il = 1, iw = 2;
    for (int i = 0; i < n_in; i++){
        if (in_sizes[i] == BATCH) il = i;
        else if (in_sizes[i] == BATCH*EMBED) ie = i;
        else if (in_sizes[i] == NSROWS*EMBED) iw = i;
    }
    const float* emb    = (const float*)d_in[ie];
    const void*  labels = (const void*)d_in[il];
    const float* W      = (const float*)d_in[iw];

    cudaFuncSetAttribute(arc_main, cudaFuncAttributeMaxDynamicSharedMemorySize, SMEM_BYTES);

    prep_label<<<320, 128>>>(emb, W, labels);
    arc_main<<<NCTAS, THREADS, SMEM_BYTES>>>(W, (float*)d_out);
}